// round 11
// baseline (speedup 1.0000x reference)
#include <cuda_runtime.h>
#include <cuda_fp16.h>
#include <cstdint>
#include <cstddef>

// ---------------------------------------------------------------------------
// GIN forward on GB300 — R11
//   R10 (fp16 2-term GEMMs) + MMA dependency-chain fix: hi-pass then lo-pass
//   over accumulators so no back-to-back RAW on the same acc registers.
// ---------------------------------------------------------------------------

#define NNODES 100000
#define MPAD   (NNODES + 128)
#define EMAX   1700000
#define WTOTAL 172032

__device__ float g_h[(size_t)NNODES * 128];
__device__ __half g_zhi[(size_t)MPAD * 128];
__device__ __half g_zlo[(size_t)MPAD * 128];
__device__ __half g_thi[(size_t)MPAD * 256];
__device__ __half g_tlo[(size_t)MPAD * 256];
__device__ int    g_is64;
__device__ __half g_whi[WTOTAL];
// CSR scratch
__device__ int g_deg[NNODES];
__device__ int g_off[NNODES];
__device__ int g_cur[NNODES];
__device__ int g_nbr[EMAX];
__device__ int g_alloc;

// ---------------------------------------------------------------------------
// Edge-index helpers
// ---------------------------------------------------------------------------
__global__ void detect_kernel(const int* __restrict__ p) {
    if (threadIdx.x == 0 && blockIdx.x == 0) {
        int is64 = 1;
        for (int j = 0; j < 128; j++) {
            if (p[2 * j + 1] != 0) { is64 = 0; break; }
        }
        g_is64 = is64;
    }
}

__device__ __forceinline__ int edge_at(const void* p, long long i) {
    return g_is64 ? (int)((const long long*)p)[i] : ((const int*)p)[i];
}

// ---------------------------------------------------------------------------
// CSR build
// ---------------------------------------------------------------------------
__global__ void hist_kernel(const void* __restrict__ eidx, int E) {
    int e = blockIdx.x * blockDim.x + threadIdx.x;
    if (e >= E) return;
    atomicAdd(&g_deg[edge_at(eidx, (long long)E + e)], 1);
}

__global__ void offsets_kernel(int n) {
    const int tid = threadIdx.x;
    const int i = blockIdx.x * 256 + tid;
    const int d = (i < n) ? g_deg[i] : 0;

    int x = d;
    #pragma unroll
    for (int o = 1; o < 32; o <<= 1) {
        int v = __shfl_up_sync(0xffffffffu, x, o);
        if ((tid & 31) >= o) x += v;
    }
    __shared__ int wsum[8];
    __shared__ int base;
    if ((tid & 31) == 31) wsum[tid >> 5] = x;
    __syncthreads();
    if (tid < 32) {
        int w = (tid < 8) ? wsum[tid] : 0;
        #pragma unroll
        for (int o = 1; o < 8; o <<= 1) {
            int v = __shfl_up_sync(0xffffffffu, w, o);
            if (tid >= o) w += v;
        }
        if (tid < 8) wsum[tid] = w;
        if (tid == 7) base = atomicAdd(&g_alloc, w);
    }
    __syncthreads();
    int excl = x - d + ((tid >= 32) ? wsum[(tid >> 5) - 1] : 0);
    if (i < n) {
        int st = base + excl;
        g_off[i] = st;
        g_cur[i] = st;
    }
}

__global__ void fill_kernel(const void* __restrict__ eidx, int E) {
    int e = blockIdx.x * blockDim.x + threadIdx.x;
    if (e >= E) return;
    int s = edge_at(eidx, e);
    int d = edge_at(eidx, (long long)E + e);
    int pos = atomicAdd(&g_cur[d], 1);
    g_nbr[pos] = s;
}

// ---------------------------------------------------------------------------
// Aggregation: one warp per node. z = (1+eps)*h[i] + sum_nbr h[j] -> fp16 hi/lo
// ---------------------------------------------------------------------------
__device__ __forceinline__ uint32_t pack_h2(__half x, __half y) {
    __half2 p = __halves2half2(x, y);
    return *reinterpret_cast<uint32_t*>(&p);
}

__global__ void agg_kernel(const float* __restrict__ h,
                           __half* __restrict__ zhi,
                           __half* __restrict__ zlo,
                           const float* __restrict__ eps, int M) {
    int warp = (blockIdx.x * blockDim.x + threadIdx.x) >> 5;
    int lane = threadIdx.x & 31;
    if (warp >= M) return;
    const float4* hp = (const float4*)h;

    float4 acc = hp[(size_t)warp * 32 + lane];
    float se = 1.0f + __ldg(eps);
    acc.x *= se; acc.y *= se; acc.z *= se; acc.w *= se;

    int p   = g_off[warp];
    int end = p + g_deg[warp];
    for (; p + 4 <= end; p += 4) {
        int j0 = g_nbr[p], j1 = g_nbr[p + 1], j2 = g_nbr[p + 2], j3 = g_nbr[p + 3];
        float4 v0 = hp[(size_t)j0 * 32 + lane];
        float4 v1 = hp[(size_t)j1 * 32 + lane];
        float4 v2 = hp[(size_t)j2 * 32 + lane];
        float4 v3 = hp[(size_t)j3 * 32 + lane];
        acc.x += v0.x + v1.x + v2.x + v3.x;
        acc.y += v0.y + v1.y + v2.y + v3.y;
        acc.z += v0.z + v1.z + v2.z + v3.z;
        acc.w += v0.w + v1.w + v2.w + v3.w;
    }
    for (; p < end; p++) {
        float4 v = hp[(size_t)g_nbr[p] * 32 + lane];
        acc.x += v.x; acc.y += v.y; acc.z += v.z; acc.w += v.w;
    }

    __half h0 = __float2half_rn(acc.x), h1 = __float2half_rn(acc.y);
    __half h2 = __float2half_rn(acc.z), h3 = __float2half_rn(acc.w);
    __half l0 = __float2half_rn(acc.x - __half2float(h0));
    __half l1 = __float2half_rn(acc.y - __half2float(h1));
    __half l2 = __float2half_rn(acc.z - __half2float(h2));
    __half l3 = __float2half_rn(acc.w - __half2float(h3));
    size_t o = (size_t)warp * 128 + lane * 4;
    *(uint2*)&zhi[o] = make_uint2(pack_h2(h0, h1), pack_h2(h2, h3));
    *(uint2*)&zlo[o] = make_uint2(pack_h2(l0, l1), pack_h2(l2, l3));
}

// ---------------------------------------------------------------------------
// Weight prep (all 7): W[K][N] fp32 -> transposed fp16 [N][K]
// ---------------------------------------------------------------------------
struct WSeg { const float* src; int K, N, off; };
struct WAll { WSeg s[7]; };

__global__ void wprep_all(WAll wa, __half* __restrict__ hi) {
    int i = blockIdx.x * blockDim.x + threadIdx.x;
    #pragma unroll
    for (int j = 0; j < 7; j++) {
        WSeg sg = wa.s[j];
        int loc = i - sg.off;
        if (loc >= 0 && loc < sg.K * sg.N) {
            int k = loc / sg.N, n = loc % sg.N;
            hi[sg.off + n * sg.K + k] = __float2half_rn(sg.src[loc]);
        }
    }
}

// x [M,64] fp32 -> split fp16
__global__ void xprep_kernel(const float* __restrict__ x,
                             __half* __restrict__ hi,
                             __half* __restrict__ lo, int n) {
    int i = blockIdx.x * blockDim.x + threadIdx.x;
    if (i >= n) return;
    float v = x[i];
    __half h = __float2half_rn(v);
    hi[i] = h;
    lo[i] = __float2half_rn(v - __half2float(h));
}

// ---------------------------------------------------------------------------
// MMA helpers (fp16)
// ---------------------------------------------------------------------------
__device__ __forceinline__ void mma_f16(float c[4], const uint32_t a[4],
                                        uint32_t b0, uint32_t b1) {
    asm volatile(
        "mma.sync.aligned.m16n8k16.row.col.f32.f16.f16.f32 "
        "{%0,%1,%2,%3}, {%4,%5,%6,%7}, {%8,%9}, {%0,%1,%2,%3};"
        : "+f"(c[0]), "+f"(c[1]), "+f"(c[2]), "+f"(c[3])
        : "r"(a[0]), "r"(a[1]), "r"(a[2]), "r"(a[3]), "r"(b0), "r"(b1));
}

__device__ __forceinline__ void ldsm_x4(uint32_t r[4], uint32_t saddr) {
    asm volatile("ldmatrix.sync.aligned.m8n8.x4.shared.b16 {%0,%1,%2,%3}, [%4];"
                 : "=r"(r[0]), "=r"(r[1]), "=r"(r[2]), "=r"(r[3])
                 : "r"(saddr));
}

__device__ __forceinline__ void cp16(uint32_t saddr, const void* gaddr) {
    asm volatile("cp.async.ca.shared.global [%0], [%1], 16;"
                 :: "r"(saddr), "l"(gaddr) : "memory");
}

// ---------------------------------------------------------------------------
// 2-term fp16 tensor-core GEMM: C = act((Ah+Al) @ Wh + bias)
// CTA tile 128x128, BK=32, 8 warps (4x2), warp 32x64.
// hi-pass then lo-pass over all accumulators (no adjacent RAW on acc).
// ---------------------------------------------------------------------------
#define STG_ELEM  5120                    // 128*40 halves per array
#define STG_BYTES (3 * STG_ELEM * 2)      // 30720 bytes per stage

template <int K, int NTOT, bool RELU, bool SPLITOUT>
__global__ __launch_bounds__(256, 2) void mma_gemm(
    const __half* __restrict__ Ahi_g,
    const __half* __restrict__ Alo_g,
    const __half* __restrict__ Wh,
    const float* __restrict__ bias,
    float* __restrict__ C,
    __half* __restrict__ Chi,
    __half* __restrict__ Clo,
    int M) {

    extern __shared__ __half smem[];
    const uint32_t sbase = (uint32_t)__cvta_generic_to_shared(smem);

    const int tid  = threadIdx.x;
    const int lane = tid & 31;
    const int warp = tid >> 5;
    const int wm   = warp >> 1;
    const int wn   = warp & 1;
    const int m0   = blockIdx.x * 128;
    const int n0   = blockIdx.y * 128;
    const int g    = lane >> 2;
    const int q4   = lane & 3;

    const int arow = (lane & 7) + ((lane >> 3) & 1) * 8;
    const int akq  = (lane >> 4) * 8;
    const int bn   = (lane & 7) + ((lane >> 4) & 1) * 8;
    const int bkq  = ((lane >> 3) & 1) * 8;

    uint32_t aBase[2], bBase[4];
    #pragma unroll
    for (int mt = 0; mt < 2; mt++) {
        int r = wm * 32 + mt * 16 + arow;
        aBase[mt] = sbase + (uint32_t)(r * 40 + akq) * 2;
    }
    #pragma unroll
    for (int ntp = 0; ntp < 4; ntp++) {
        int n = wn * 64 + ntp * 16 + bn;
        bBase[ntp] = sbase + (uint32_t)(2 * STG_ELEM + n * 40 + bkq) * 2;
    }

    auto issue_tile = [&](int s, int k0) {
        uint32_t b = sbase + (uint32_t)s * STG_BYTES;
        #pragma unroll
        for (int rep = 0; rep < 2; rep++) {
            int i = tid + rep * 256;
            int row = i >> 2, q = i & 3;
            uint32_t so = (uint32_t)(row * 40 + q * 8) * 2;
            size_t ga = (size_t)(m0 + row) * K + k0 + q * 8;
            size_t gb = (size_t)(n0 + row) * K + k0 + q * 8;
            cp16(b + so, Ahi_g + ga);
            cp16(b + STG_ELEM * 2 + so, Alo_g + ga);
            cp16(b + 2 * STG_ELEM * 2 + so, Wh + gb);
        }
        asm volatile("cp.async.commit_group;");
    };

    float acc[2][8][4];
    #pragma unroll
    for (int mt = 0; mt < 2; mt++)
        #pragma unroll
        for (int nt = 0; nt < 8; nt++)
            #pragma unroll
            for (int j = 0; j < 4; j++) acc[mt][nt][j] = 0.0f;

    constexpr int NIT = K / 32;
    issue_tile(0, 0);

    #pragma unroll
    for (int it = 0; it < NIT; it++) {
        if (it + 1 < NIT) {
            issue_tile((it + 1) & 1, (it + 1) * 32);
            asm volatile("cp.async.wait_group 1;");
        } else {
            asm volatile("cp.async.wait_group 0;");
        }
        __syncthreads();

        const uint32_t st = (uint32_t)(it & 1) * STG_BYTES;
        #pragma unroll
        for (int ks = 0; ks < 32; ks += 16) {
            const uint32_t kofs = st + (uint32_t)ks * 2;
            uint32_t ah[2][4], al[2][4];
            #pragma unroll
            for (int mt = 0; mt < 2; mt++) {
                ldsm_x4(ah[mt], aBase[mt] + kofs);
                ldsm_x4(al[mt], aBase[mt] + STG_ELEM * 2 + kofs);
            }
            uint32_t bh[4][4];
            #pragma unroll
            for (int ntp = 0; ntp < 4; ntp++)
                ldsm_x4(bh[ntp], bBase[ntp] + kofs);
            // hi pass: 16 independent accumulators
            #pragma unroll
            for (int nt = 0; nt < 8; nt++) {
                uint32_t b0 = bh[nt >> 1][(nt & 1) * 2];
                uint32_t b1 = bh[nt >> 1][(nt & 1) * 2 + 1];
                #pragma unroll
                for (int mt = 0; mt < 2; mt++)
                    mma_f16(acc[mt][nt], ah[mt], b0, b1);
            }
            // lo pass: same accs, 16 MMAs later -> latency covered
            #pragma unroll
            for (int nt = 0; nt < 8; nt++) {
                uint32_t b0 = bh[nt >> 1][(nt & 1) * 2];
                uint32_t b1 = bh[nt >> 1][(nt & 1) * 2 + 1];
                #pragma unroll
                for (int mt = 0; mt < 2; mt++)
                    mma_f16(acc[mt][nt], al[mt], b0, b1);
            }
        }
        __syncthreads();
    }

    // ---- epilogue ----
    #pragma unroll
    for (int mt = 0; mt < 2; mt++) {
        #pragma unroll
        for (int nt = 0; nt < 8; nt++) {
            int c = n0 + wn * 64 + nt * 8 + 2 * q4;
            float2 bv = make_float2(0.f, 0.f);
            if (bias) bv = *(const float2*)&bias[c];
            int r = m0 + wm * 32 + mt * 16 + g;
            float2 o0, o1;
            o0.x = acc[mt][nt][0] + bv.x;
            o0.y = acc[mt][nt][1] + bv.y;
            o1.x = acc[mt][nt][2] + bv.x;
            o1.y = acc[mt][nt][3] + bv.y;
            if (RELU) {
                o0.x = fmaxf(o0.x, 0.f); o0.y = fmaxf(o0.y, 0.f);
                o1.x = fmaxf(o1.x, 0.f); o1.y = fmaxf(o1.y, 0.f);
            }
            #pragma unroll
            for (int half = 0; half < 2; half++) {
                int rr = r + half * 8;
                float2 o = half ? o1 : o0;
                if (rr < M) {
                    if (SPLITOUT) {
                        __half hx = __float2half_rn(o.x);
                        __half hy = __float2half_rn(o.y);
                        __half lx = __float2half_rn(o.x - __half2float(hx));
                        __half ly = __float2half_rn(o.y - __half2float(hy));
                        *(uint32_t*)&Chi[(size_t)rr * NTOT + c] = pack_h2(hx, hy);
                        *(uint32_t*)&Clo[(size_t)rr * NTOT + c] = pack_h2(lx, ly);
                    } else {
                        *(float2*)&C[(size_t)rr * NTOT + c] = o;
                    }
                }
            }
        }
    }
}

// ---------------------------------------------------------------------------
// Host side
// ---------------------------------------------------------------------------
static __half* s_whi;

template <int K, int NTOT, bool RELU, bool SPLITOUT>
static void run_gemm(const __half* Ahi, const __half* Alo,
                     int woff, const float* bias,
                     float* C, __half* Chi, __half* Clo, int M) {
    cudaFuncSetAttribute(mma_gemm<K, NTOT, RELU, SPLITOUT>,
                         cudaFuncAttributeMaxDynamicSharedMemorySize,
                         2 * STG_BYTES);
    dim3 grid((M + 127) / 128, NTOT / 128);
    mma_gemm<K, NTOT, RELU, SPLITOUT><<<grid, 256, 2 * STG_BYTES>>>(
        Ahi, Alo, s_whi + woff, bias, C, Chi, Clo, M);
}

extern "C" void kernel_launch(void* const* d_in, const int* in_sizes, int n_in,
                              void* d_out, int out_size) {
    const float* x       = (const float*)d_in[0];
    const void*  eidx    = d_in[1];
    const float* W_embed = (const float*)d_in[2];
    const float* eps1    = (const float*)d_in[3];
    const float* w1a     = (const float*)d_in[4];
    const float* b1a     = (const float*)d_in[5];
    const float* w1b     = (const float*)d_in[6];
    const float* b1b     = (const float*)d_in[7];
    const float* eps2    = (const float*)d_in[8];
    const float* w2a     = (const float*)d_in[9];
    const float* b2a     = (const float*)d_in[10];
    const float* w2b     = (const float*)d_in[11];
    const float* b2b     = (const float*)d_in[12];
    const float* eps3    = (const float*)d_in[13];
    const float* w3a     = (const float*)d_in[14];
    const float* b3a     = (const float*)d_in[15];
    const float* w3b     = (const float*)d_in[16];
    const float* b3b     = (const float*)d_in[17];

    const int M = in_sizes[0] / 64;
    const int E = in_sizes[1] / 2;

    float* ph;
    __half *pzhi, *pzlo, *pthi, *ptlo;
    int *pdeg, *palloc;
    cudaGetSymbolAddress((void**)&ph,   g_h);
    cudaGetSymbolAddress((void**)&pzhi, g_zhi);
    cudaGetSymbolAddress((void**)&pzlo, g_zlo);
    cudaGetSymbolAddress((void**)&pthi, g_thi);
    cudaGetSymbolAddress((void**)&ptlo, g_tlo);
    cudaGetSymbolAddress((void**)&s_whi, g_whi);
    cudaGetSymbolAddress((void**)&pdeg, g_deg);
    cudaGetSymbolAddress((void**)&palloc, g_alloc);
    float* out = (float*)d_out;

    const int eBlks   = (E + 255) / 256;
    const int aggBlks = (M + 7) / 8;

    static cudaStream_t s1 = nullptr;
    static cudaEvent_t evFork = nullptr, evJoin = nullptr;
    if (!s1) {
        cudaStreamCreateWithFlags(&s1, cudaStreamNonBlocking);
        cudaEventCreateWithFlags(&evFork, cudaEventDisableTiming);
        cudaEventCreateWithFlags(&evJoin, cudaEventDisableTiming);
    }

    // ---- fork: CSR build on s1 ----
    cudaEventRecord(evFork, 0);
    cudaStreamWaitEvent(s1, evFork, 0);

    cudaMemsetAsync(pdeg, 0, (size_t)M * sizeof(int), s1);
    cudaMemsetAsync(palloc, 0, sizeof(int), s1);
    detect_kernel<<<1, 1, 0, s1>>>((const int*)eidx);
    hist_kernel<<<eBlks, 256, 0, s1>>>(eidx, E);
    offsets_kernel<<<(M + 255) / 256, 256, 0, s1>>>(M);
    fill_kernel<<<eBlks, 256, 0, s1>>>(eidx, E);
    cudaEventRecord(evJoin, s1);

    // ---- main stream: weights + x split + embed ----
    WAll wa;
    wa.s[0] = {W_embed,  64, 128, 0};
    wa.s[1] = {w1a, 128, 128, 8192};
    wa.s[2] = {w1b, 128, 128, 24576};
    wa.s[3] = {w2a, 128, 256, 40960};
    wa.s[4] = {w2b, 256, 128, 73728};
    wa.s[5] = {w3a, 128, 256, 106496};
    wa.s[6] = {w3b, 256, 128, 139264};
    wprep_all<<<(WTOTAL + 255) / 256, 256>>>(wa, s_whi);

    xprep_kernel<<<(M * 64 + 255) / 256, 256>>>(x, pthi, ptlo, M * 64);

    // embed: h = x @ W_embed
    run_gemm<64, 128, false, false>(pthi, ptlo, 0, nullptr,
                                    ph, nullptr, nullptr, M);

    cudaStreamWaitEvent(0, evJoin, 0);

    // ---- conv1 ----
    agg_kernel<<<aggBlks, 256>>>(ph, pzhi, pzlo, eps1, M);
    run_gemm<128, 128, true,  true >(pzhi, pzlo, 8192,  b1a,
                                     nullptr, pthi, ptlo, M);
    run_gemm<128, 128, false, false>(pthi, ptlo, 24576, b1b,
                                     ph, nullptr, nullptr, M);

    // ---- conv2 ----
    agg_kernel<<<aggBlks, 256>>>(ph, pzhi, pzlo, eps2, M);
    run_gemm<128, 256, true, true >(pzhi, pzlo, 40960, b2a,
                                    nullptr, pthi, ptlo, M);
    run_gemm<256, 128, true, false>(pthi, ptlo, 73728, b2b,
                                    ph, nullptr, nullptr, M);

    // ---- conv3 ----
    agg_kernel<<<aggBlks, 256>>>(ph, pzhi, pzlo, eps3, M);
    run_gemm<128, 256, true, true >(pzhi, pzlo, 106496, b3a,
                                    nullptr, pthi, ptlo, M);
    run_gemm<256, 128, true, false>(pthi, ptlo, 139264, b3b,
                                    out, nullptr, nullptr, M);
}

// round 16
// speedup vs baseline: 1.0438x; 1.0438x over previous
#include <cuda_runtime.h>
#include <cuda_fp16.h>
#include <cstdint>
#include <cstddef>

// ---------------------------------------------------------------------------
// GIN forward on GB300 — R12
//   R11 + fp16 inter-layer activations h (halves aggregation L2 traffic;
//   aggregation sum stays fp32, z still split hi/lo for GEMM precision).
// ---------------------------------------------------------------------------

#define NNODES 100000
#define MPAD   (NNODES + 128)
#define EMAX   1700000
#define WTOTAL 172032

__device__ __half g_h16[(size_t)NNODES * 128];
__device__ __half g_zhi[(size_t)MPAD * 128];
__device__ __half g_zlo[(size_t)MPAD * 128];
__device__ __half g_thi[(size_t)MPAD * 256];
__device__ __half g_tlo[(size_t)MPAD * 256];
__device__ int    g_is64;
__device__ __half g_whi[WTOTAL];
// CSR scratch
__device__ int g_deg[NNODES];
__device__ int g_off[NNODES];
__device__ int g_cur[NNODES];
__device__ int g_nbr[EMAX];
__device__ int g_alloc;

// ---------------------------------------------------------------------------
// Edge-index helpers
// ---------------------------------------------------------------------------
__global__ void detect_kernel(const int* __restrict__ p) {
    if (threadIdx.x == 0 && blockIdx.x == 0) {
        int is64 = 1;
        for (int j = 0; j < 128; j++) {
            if (p[2 * j + 1] != 0) { is64 = 0; break; }
        }
        g_is64 = is64;
    }
}

__device__ __forceinline__ int edge_at(const void* p, long long i) {
    return g_is64 ? (int)((const long long*)p)[i] : ((const int*)p)[i];
}

// ---------------------------------------------------------------------------
// CSR build
// ---------------------------------------------------------------------------
__global__ void hist_kernel(const void* __restrict__ eidx, int E) {
    int e = blockIdx.x * blockDim.x + threadIdx.x;
    if (e >= E) return;
    atomicAdd(&g_deg[edge_at(eidx, (long long)E + e)], 1);
}

__global__ void offsets_kernel(int n) {
    const int tid = threadIdx.x;
    const int i = blockIdx.x * 256 + tid;
    const int d = (i < n) ? g_deg[i] : 0;

    int x = d;
    #pragma unroll
    for (int o = 1; o < 32; o <<= 1) {
        int v = __shfl_up_sync(0xffffffffu, x, o);
        if ((tid & 31) >= o) x += v;
    }
    __shared__ int wsum[8];
    __shared__ int base;
    if ((tid & 31) == 31) wsum[tid >> 5] = x;
    __syncthreads();
    if (tid < 32) {
        int w = (tid < 8) ? wsum[tid] : 0;
        #pragma unroll
        for (int o = 1; o < 8; o <<= 1) {
            int v = __shfl_up_sync(0xffffffffu, w, o);
            if (tid >= o) w += v;
        }
        if (tid < 8) wsum[tid] = w;
        if (tid == 7) base = atomicAdd(&g_alloc, w);
    }
    __syncthreads();
    int excl = x - d + ((tid >= 32) ? wsum[(tid >> 5) - 1] : 0);
    if (i < n) {
        int st = base + excl;
        g_off[i] = st;
        g_cur[i] = st;
    }
}

__global__ void fill_kernel(const void* __restrict__ eidx, int E) {
    int e = blockIdx.x * blockDim.x + threadIdx.x;
    if (e >= E) return;
    int s = edge_at(eidx, e);
    int d = edge_at(eidx, (long long)E + e);
    int pos = atomicAdd(&g_cur[d], 1);
    g_nbr[pos] = s;
}

// ---------------------------------------------------------------------------
// Aggregation: one warp per node, h in fp16 (gather 256B rows), sum fp32.
// z = (1+eps)*h[i] + sum_nbr h[j]  -> fp16 hi/lo.
// Lane handles 4 halves (uint2).
// ---------------------------------------------------------------------------
__device__ __forceinline__ uint32_t pack_h2(__half x, __half y) {
    __half2 p = __halves2half2(x, y);
    return *reinterpret_cast<uint32_t*>(&p);
}

__device__ __forceinline__ float4 up4(uint2 u) {
    __half2 a = *reinterpret_cast<__half2*>(&u.x);
    __half2 b = *reinterpret_cast<__half2*>(&u.y);
    float2 fa = __half22float2(a), fb = __half22float2(b);
    return make_float4(fa.x, fa.y, fb.x, fb.y);
}

__global__ void agg_kernel(const __half* __restrict__ h,
                           __half* __restrict__ zhi,
                           __half* __restrict__ zlo,
                           const float* __restrict__ eps, int M) {
    int warp = (blockIdx.x * blockDim.x + threadIdx.x) >> 5;
    int lane = threadIdx.x & 31;
    if (warp >= M) return;
    const uint2* hp = (const uint2*)h;     // 4 halves per entry, 32/row

    float4 acc = up4(hp[(size_t)warp * 32 + lane]);
    float se = 1.0f + __ldg(eps);
    acc.x *= se; acc.y *= se; acc.z *= se; acc.w *= se;

    int p   = g_off[warp];
    int end = p + g_deg[warp];
    for (; p + 4 <= end; p += 4) {
        int j0 = g_nbr[p], j1 = g_nbr[p + 1], j2 = g_nbr[p + 2], j3 = g_nbr[p + 3];
        float4 v0 = up4(hp[(size_t)j0 * 32 + lane]);
        float4 v1 = up4(hp[(size_t)j1 * 32 + lane]);
        float4 v2 = up4(hp[(size_t)j2 * 32 + lane]);
        float4 v3 = up4(hp[(size_t)j3 * 32 + lane]);
        acc.x += v0.x + v1.x + v2.x + v3.x;
        acc.y += v0.y + v1.y + v2.y + v3.y;
        acc.z += v0.z + v1.z + v2.z + v3.z;
        acc.w += v0.w + v1.w + v2.w + v3.w;
    }
    for (; p < end; p++) {
        float4 v = up4(hp[(size_t)g_nbr[p] * 32 + lane]);
        acc.x += v.x; acc.y += v.y; acc.z += v.z; acc.w += v.w;
    }

    __half h0 = __float2half_rn(acc.x), h1 = __float2half_rn(acc.y);
    __half h2 = __float2half_rn(acc.z), h3 = __float2half_rn(acc.w);
    __half l0 = __float2half_rn(acc.x - __half2float(h0));
    __half l1 = __float2half_rn(acc.y - __half2float(h1));
    __half l2 = __float2half_rn(acc.z - __half2float(h2));
    __half l3 = __float2half_rn(acc.w - __half2float(h3));
    size_t o = (size_t)warp * 128 + lane * 4;
    *(uint2*)&zhi[o] = make_uint2(pack_h2(h0, h1), pack_h2(h2, h3));
    *(uint2*)&zlo[o] = make_uint2(pack_h2(l0, l1), pack_h2(l2, l3));
}

// ---------------------------------------------------------------------------
// Weight prep (all 7): W[K][N] fp32 -> transposed fp16 [N][K]
// ---------------------------------------------------------------------------
struct WSeg { const float* src; int K, N, off; };
struct WAll { WSeg s[7]; };

__global__ void wprep_all(WAll wa, __half* __restrict__ hi) {
    int i = blockIdx.x * blockDim.x + threadIdx.x;
    #pragma unroll
    for (int j = 0; j < 7; j++) {
        WSeg sg = wa.s[j];
        int loc = i - sg.off;
        if (loc >= 0 && loc < sg.K * sg.N) {
            int k = loc / sg.N, n = loc % sg.N;
            hi[sg.off + n * sg.K + k] = __float2half_rn(sg.src[loc]);
        }
    }
}

// x [M,64] fp32 -> split fp16
__global__ void xprep_kernel(const float* __restrict__ x,
                             __half* __restrict__ hi,
                             __half* __restrict__ lo, int n) {
    int i = blockIdx.x * blockDim.x + threadIdx.x;
    if (i >= n) return;
    float v = x[i];
    __half h = __float2half_rn(v);
    hi[i] = h;
    lo[i] = __float2half_rn(v - __half2float(h));
}

// ---------------------------------------------------------------------------
// MMA helpers (fp16)
// ---------------------------------------------------------------------------
__device__ __forceinline__ void mma_f16(float c[4], const uint32_t a[4],
                                        uint32_t b0, uint32_t b1) {
    asm volatile(
        "mma.sync.aligned.m16n8k16.row.col.f32.f16.f16.f32 "
        "{%0,%1,%2,%3}, {%4,%5,%6,%7}, {%8,%9}, {%0,%1,%2,%3};"
        : "+f"(c[0]), "+f"(c[1]), "+f"(c[2]), "+f"(c[3])
        : "r"(a[0]), "r"(a[1]), "r"(a[2]), "r"(a[3]), "r"(b0), "r"(b1));
}

__device__ __forceinline__ void ldsm_x4(uint32_t r[4], uint32_t saddr) {
    asm volatile("ldmatrix.sync.aligned.m8n8.x4.shared.b16 {%0,%1,%2,%3}, [%4];"
                 : "=r"(r[0]), "=r"(r[1]), "=r"(r[2]), "=r"(r[3])
                 : "r"(saddr));
}

__device__ __forceinline__ void cp16(uint32_t saddr, const void* gaddr) {
    asm volatile("cp.async.ca.shared.global [%0], [%1], 16;"
                 :: "r"(saddr), "l"(gaddr) : "memory");
}

// ---------------------------------------------------------------------------
// 2-term fp16 tensor-core GEMM: C = act((Ah+Al) @ Wh + bias)
// CTA tile 128x128, BK=32, 8 warps (4x2), warp 32x64.
// OUTM: 0 = fp32 C, 1 = split fp16 hi/lo (Chi/Clo), 2 = fp16 (Chi).
// ---------------------------------------------------------------------------
#define STG_ELEM  5120                    // 128*40 halves per array
#define STG_BYTES (3 * STG_ELEM * 2)      // 30720 bytes per stage

template <int K, int NTOT, bool RELU, int OUTM>
__global__ __launch_bounds__(256, 2) void mma_gemm(
    const __half* __restrict__ Ahi_g,
    const __half* __restrict__ Alo_g,
    const __half* __restrict__ Wh,
    const float* __restrict__ bias,
    float* __restrict__ C,
    __half* __restrict__ Chi,
    __half* __restrict__ Clo,
    int M) {

    extern __shared__ __half smem[];
    const uint32_t sbase = (uint32_t)__cvta_generic_to_shared(smem);

    const int tid  = threadIdx.x;
    const int lane = tid & 31;
    const int warp = tid >> 5;
    const int wm   = warp >> 1;
    const int wn   = warp & 1;
    const int m0   = blockIdx.x * 128;
    const int n0   = blockIdx.y * 128;
    const int g    = lane >> 2;
    const int q4   = lane & 3;

    const int arow = (lane & 7) + ((lane >> 3) & 1) * 8;
    const int akq  = (lane >> 4) * 8;
    const int bn   = (lane & 7) + ((lane >> 4) & 1) * 8;
    const int bkq  = ((lane >> 3) & 1) * 8;

    uint32_t aBase[2], bBase[4];
    #pragma unroll
    for (int mt = 0; mt < 2; mt++) {
        int r = wm * 32 + mt * 16 + arow;
        aBase[mt] = sbase + (uint32_t)(r * 40 + akq) * 2;
    }
    #pragma unroll
    for (int ntp = 0; ntp < 4; ntp++) {
        int n = wn * 64 + ntp * 16 + bn;
        bBase[ntp] = sbase + (uint32_t)(2 * STG_ELEM + n * 40 + bkq) * 2;
    }

    auto issue_tile = [&](int s, int k0) {
        uint32_t b = sbase + (uint32_t)s * STG_BYTES;
        #pragma unroll
        for (int rep = 0; rep < 2; rep++) {
            int i = tid + rep * 256;
            int row = i >> 2, q = i & 3;
            uint32_t so = (uint32_t)(row * 40 + q * 8) * 2;
            size_t ga = (size_t)(m0 + row) * K + k0 + q * 8;
            size_t gb = (size_t)(n0 + row) * K + k0 + q * 8;
            cp16(b + so, Ahi_g + ga);
            cp16(b + STG_ELEM * 2 + so, Alo_g + ga);
            cp16(b + 2 * STG_ELEM * 2 + so, Wh + gb);
        }
        asm volatile("cp.async.commit_group;");
    };

    float acc[2][8][4];
    #pragma unroll
    for (int mt = 0; mt < 2; mt++)
        #pragma unroll
        for (int nt = 0; nt < 8; nt++)
            #pragma unroll
            for (int j = 0; j < 4; j++) acc[mt][nt][j] = 0.0f;

    constexpr int NIT = K / 32;
    issue_tile(0, 0);

    #pragma unroll
    for (int it = 0; it < NIT; it++) {
        if (it + 1 < NIT) {
            issue_tile((it + 1) & 1, (it + 1) * 32);
            asm volatile("cp.async.wait_group 1;");
        } else {
            asm volatile("cp.async.wait_group 0;");
        }
        __syncthreads();

        const uint32_t st = (uint32_t)(it & 1) * STG_BYTES;
        #pragma unroll
        for (int ks = 0; ks < 32; ks += 16) {
            const uint32_t kofs = st + (uint32_t)ks * 2;
            uint32_t ah[2][4], al[2][4];
            #pragma unroll
            for (int mt = 0; mt < 2; mt++) {
                ldsm_x4(ah[mt], aBase[mt] + kofs);
                ldsm_x4(al[mt], aBase[mt] + STG_ELEM * 2 + kofs);
            }
            uint32_t bh[4][4];
            #pragma unroll
            for (int ntp = 0; ntp < 4; ntp++)
                ldsm_x4(bh[ntp], bBase[ntp] + kofs);
            #pragma unroll
            for (int nt = 0; nt < 8; nt++) {
                uint32_t b0 = bh[nt >> 1][(nt & 1) * 2];
                uint32_t b1 = bh[nt >> 1][(nt & 1) * 2 + 1];
                #pragma unroll
                for (int mt = 0; mt < 2; mt++)
                    mma_f16(acc[mt][nt], ah[mt], b0, b1);
            }
            #pragma unroll
            for (int nt = 0; nt < 8; nt++) {
                uint32_t b0 = bh[nt >> 1][(nt & 1) * 2];
                uint32_t b1 = bh[nt >> 1][(nt & 1) * 2 + 1];
                #pragma unroll
                for (int mt = 0; mt < 2; mt++)
                    mma_f16(acc[mt][nt], al[mt], b0, b1);
            }
        }
        __syncthreads();
    }

    // ---- epilogue ----
    #pragma unroll
    for (int mt = 0; mt < 2; mt++) {
        #pragma unroll
        for (int nt = 0; nt < 8; nt++) {
            int c = n0 + wn * 64 + nt * 8 + 2 * q4;
            float2 bv = make_float2(0.f, 0.f);
            if (bias) bv = *(const float2*)&bias[c];
            int r = m0 + wm * 32 + mt * 16 + g;
            float2 o0, o1;
            o0.x = acc[mt][nt][0] + bv.x;
            o0.y = acc[mt][nt][1] + bv.y;
            o1.x = acc[mt][nt][2] + bv.x;
            o1.y = acc[mt][nt][3] + bv.y;
            if (RELU) {
                o0.x = fmaxf(o0.x, 0.f); o0.y = fmaxf(o0.y, 0.f);
                o1.x = fmaxf(o1.x, 0.f); o1.y = fmaxf(o1.y, 0.f);
            }
            #pragma unroll
            for (int half = 0; half < 2; half++) {
                int rr = r + half * 8;
                float2 o = half ? o1 : o0;
                if (rr < M) {
                    if (OUTM == 1) {
                        __half hx = __float2half_rn(o.x);
                        __half hy = __float2half_rn(o.y);
                        __half lx = __float2half_rn(o.x - __half2float(hx));
                        __half ly = __float2half_rn(o.y - __half2float(hy));
                        *(uint32_t*)&Chi[(size_t)rr * NTOT + c] = pack_h2(hx, hy);
                        *(uint32_t*)&Clo[(size_t)rr * NTOT + c] = pack_h2(lx, ly);
                    } else if (OUTM == 2) {
                        *(uint32_t*)&Chi[(size_t)rr * NTOT + c] =
                            pack_h2(__float2half_rn(o.x), __float2half_rn(o.y));
                    } else {
                        *(float2*)&C[(size_t)rr * NTOT + c] = o;
                    }
                }
            }
        }
    }
}

// ---------------------------------------------------------------------------
// Host side
// ---------------------------------------------------------------------------
static __half* s_whi;

template <int K, int NTOT, bool RELU, int OUTM>
static void run_gemm(const __half* Ahi, const __half* Alo,
                     int woff, const float* bias,
                     float* C, __half* Chi, __half* Clo, int M) {
    cudaFuncSetAttribute(mma_gemm<K, NTOT, RELU, OUTM>,
                         cudaFuncAttributeMaxDynamicSharedMemorySize,
                         2 * STG_BYTES);
    dim3 grid((M + 127) / 128, NTOT / 128);
    mma_gemm<K, NTOT, RELU, OUTM><<<grid, 256, 2 * STG_BYTES>>>(
        Ahi, Alo, s_whi + woff, bias, C, Chi, Clo, M);
}

extern "C" void kernel_launch(void* const* d_in, const int* in_sizes, int n_in,
                              void* d_out, int out_size) {
    const float* x       = (const float*)d_in[0];
    const void*  eidx    = d_in[1];
    const float* W_embed = (const float*)d_in[2];
    const float* eps1    = (const float*)d_in[3];
    const float* w1a     = (const float*)d_in[4];
    const float* b1a     = (const float*)d_in[5];
    const float* w1b     = (const float*)d_in[6];
    const float* b1b     = (const float*)d_in[7];
    const float* eps2    = (const float*)d_in[8];
    const float* w2a     = (const float*)d_in[9];
    const float* b2a     = (const float*)d_in[10];
    const float* w2b     = (const float*)d_in[11];
    const float* b2b     = (const float*)d_in[12];
    const float* eps3    = (const float*)d_in[13];
    const float* w3a     = (const float*)d_in[14];
    const float* b3a     = (const float*)d_in[15];
    const float* w3b     = (const float*)d_in[16];
    const float* b3b     = (const float*)d_in[17];

    const int M = in_sizes[0] / 64;
    const int E = in_sizes[1] / 2;

    __half *ph16, *pzhi, *pzlo, *pthi, *ptlo;
    int *pdeg, *palloc;
    cudaGetSymbolAddress((void**)&ph16, g_h16);
    cudaGetSymbolAddress((void**)&pzhi, g_zhi);
    cudaGetSymbolAddress((void**)&pzlo, g_zlo);
    cudaGetSymbolAddress((void**)&pthi, g_thi);
    cudaGetSymbolAddress((void**)&ptlo, g_tlo);
    cudaGetSymbolAddress((void**)&s_whi, g_whi);
    cudaGetSymbolAddress((void**)&pdeg, g_deg);
    cudaGetSymbolAddress((void**)&palloc, g_alloc);
    float* out = (float*)d_out;

    const int eBlks   = (E + 255) / 256;
    const int aggBlks = (M + 7) / 8;

    static cudaStream_t s1 = nullptr;
    static cudaEvent_t evFork = nullptr, evJoin = nullptr;
    if (!s1) {
        cudaStreamCreateWithFlags(&s1, cudaStreamNonBlocking);
        cudaEventCreateWithFlags(&evFork, cudaEventDisableTiming);
        cudaEventCreateWithFlags(&evJoin, cudaEventDisableTiming);
    }

    // ---- fork: CSR build on s1 ----
    cudaEventRecord(evFork, 0);
    cudaStreamWaitEvent(s1, evFork, 0);

    cudaMemsetAsync(pdeg, 0, (size_t)M * sizeof(int), s1);
    cudaMemsetAsync(palloc, 0, sizeof(int), s1);
    detect_kernel<<<1, 1, 0, s1>>>((const int*)eidx);
    hist_kernel<<<eBlks, 256, 0, s1>>>(eidx, E);
    offsets_kernel<<<(M + 255) / 256, 256, 0, s1>>>(M);
    fill_kernel<<<eBlks, 256, 0, s1>>>(eidx, E);
    cudaEventRecord(evJoin, s1);

    // ---- main stream: weights + x split + embed ----
    WAll wa;
    wa.s[0] = {W_embed,  64, 128, 0};
    wa.s[1] = {w1a, 128, 128, 8192};
    wa.s[2] = {w1b, 128, 128, 24576};
    wa.s[3] = {w2a, 128, 256, 40960};
    wa.s[4] = {w2b, 256, 128, 73728};
    wa.s[5] = {w3a, 128, 256, 106496};
    wa.s[6] = {w3b, 256, 128, 139264};
    wprep_all<<<(WTOTAL + 255) / 256, 256>>>(wa, s_whi);

    xprep_kernel<<<(M * 64 + 255) / 256, 256>>>(x, pthi, ptlo, M * 64);

    // embed: h = x @ W_embed  (fp16 h out)
    run_gemm<64, 128, false, 2>(pthi, ptlo, 0, nullptr,
                                nullptr, ph16, nullptr, M);

    cudaStreamWaitEvent(0, evJoin, 0);

    // ---- conv1 ----
    agg_kernel<<<aggBlks, 256>>>(ph16, pzhi, pzlo, eps1, M);
    run_gemm<128, 128, true,  1>(pzhi, pzlo, 8192,  b1a,
                                 nullptr, pthi, ptlo, M);
    run_gemm<128, 128, false, 2>(pthi, ptlo, 24576, b1b,
                                 nullptr, ph16, nullptr, M);

    // ---- conv2 ----
    agg_kernel<<<aggBlks, 256>>>(ph16, pzhi, pzlo, eps2, M);
    run_gemm<128, 256, true, 1>(pzhi, pzlo, 40960, b2a,
                                nullptr, pthi, ptlo, M);
    run_gemm<256, 128, true, 2>(pthi, ptlo, 73728, b2b,
                                nullptr, ph16, nullptr, M);

    // ---- conv3 ----
    agg_kernel<<<aggBlks, 256>>>(ph16, pzhi, pzlo, eps3, M);
    run_gemm<128, 256, true, 1>(pzhi, pzlo, 106496, b3a,
                                nullptr, pthi, ptlo, M);
    run_gemm<256, 128, true, 0>(pthi, ptlo, 139264, b3b,
                                out, nullptr, nullptr, M);
}

// round 17
// speedup vs baseline: 1.4197x; 1.3601x over previous
#include <cuda_runtime.h>
#include <cuda_fp16.h>
#include <cstdint>
#include <cstddef>

// ---------------------------------------------------------------------------
// GIN forward on GB300 — R17
//   Pure-fp16 single-pass GEMMs (activations AND weights fp16, fp32 accum).
//   CSR aggregation (fp32 sums), fp16 everywhere between kernels.
// ---------------------------------------------------------------------------

#define NNODES 100000
#define MPAD   (NNODES + 128)
#define EMAX   1700000
#define WTOTAL 172032

__device__ __half g_h16[(size_t)NNODES * 128];
__device__ __half g_z16[(size_t)MPAD * 128];
__device__ __half g_t16[(size_t)MPAD * 256];
__device__ int    g_is64;
__device__ __half g_whi[WTOTAL];
// CSR scratch
__device__ int g_deg[NNODES];
__device__ int g_off[NNODES];
__device__ int g_cur[NNODES];
__device__ int g_nbr[EMAX];
__device__ int g_alloc;

// ---------------------------------------------------------------------------
// Edge-index helpers
// ---------------------------------------------------------------------------
__global__ void detect_kernel(const int* __restrict__ p) {
    if (threadIdx.x == 0 && blockIdx.x == 0) {
        int is64 = 1;
        for (int j = 0; j < 128; j++) {
            if (p[2 * j + 1] != 0) { is64 = 0; break; }
        }
        g_is64 = is64;
    }
}

__device__ __forceinline__ int edge_at(const void* p, long long i) {
    return g_is64 ? (int)((const long long*)p)[i] : ((const int*)p)[i];
}

// ---------------------------------------------------------------------------
// CSR build
// ---------------------------------------------------------------------------
__global__ void hist_kernel(const void* __restrict__ eidx, int E) {
    int e = blockIdx.x * blockDim.x + threadIdx.x;
    if (e >= E) return;
    atomicAdd(&g_deg[edge_at(eidx, (long long)E + e)], 1);
}

__global__ void offsets_kernel(int n) {
    const int tid = threadIdx.x;
    const int i = blockIdx.x * 256 + tid;
    const int d = (i < n) ? g_deg[i] : 0;

    int x = d;
    #pragma unroll
    for (int o = 1; o < 32; o <<= 1) {
        int v = __shfl_up_sync(0xffffffffu, x, o);
        if ((tid & 31) >= o) x += v;
    }
    __shared__ int wsum[8];
    __shared__ int base;
    if ((tid & 31) == 31) wsum[tid >> 5] = x;
    __syncthreads();
    if (tid < 32) {
        int w = (tid < 8) ? wsum[tid] : 0;
        #pragma unroll
        for (int o = 1; o < 8; o <<= 1) {
            int v = __shfl_up_sync(0xffffffffu, w, o);
            if (tid >= o) w += v;
        }
        if (tid < 8) wsum[tid] = w;
        if (tid == 7) base = atomicAdd(&g_alloc, w);
    }
    __syncthreads();
    int excl = x - d + ((tid >= 32) ? wsum[(tid >> 5) - 1] : 0);
    if (i < n) {
        int st = base + excl;
        g_off[i] = st;
        g_cur[i] = st;
    }
}

__global__ void fill_kernel(const void* __restrict__ eidx, int E) {
    int e = blockIdx.x * blockDim.x + threadIdx.x;
    if (e >= E) return;
    int s = edge_at(eidx, e);
    int d = edge_at(eidx, (long long)E + e);
    int pos = atomicAdd(&g_cur[d], 1);
    g_nbr[pos] = s;
}

// ---------------------------------------------------------------------------
// Aggregation: one warp per node, h fp16 (256B rows), fp32 sums, fp16 z out.
// ---------------------------------------------------------------------------
__device__ __forceinline__ uint32_t pack_h2(__half x, __half y) {
    __half2 p = __halves2half2(x, y);
    return *reinterpret_cast<uint32_t*>(&p);
}

__device__ __forceinline__ float4 up4(uint2 u) {
    __half2 a = *reinterpret_cast<__half2*>(&u.x);
    __half2 b = *reinterpret_cast<__half2*>(&u.y);
    float2 fa = __half22float2(a), fb = __half22float2(b);
    return make_float4(fa.x, fa.y, fb.x, fb.y);
}

__global__ void agg_kernel(const __half* __restrict__ h,
                           __half* __restrict__ z,
                           const float* __restrict__ eps, int M) {
    int warp = (blockIdx.x * blockDim.x + threadIdx.x) >> 5;
    int lane = threadIdx.x & 31;
    if (warp >= M) return;
    const uint2* hp = (const uint2*)h;     // 4 halves per entry, 32/row

    float4 acc = up4(hp[(size_t)warp * 32 + lane]);
    float se = 1.0f + __ldg(eps);
    acc.x *= se; acc.y *= se; acc.z *= se; acc.w *= se;

    int p   = g_off[warp];
    int end = p + g_deg[warp];
    for (; p + 4 <= end; p += 4) {
        int j0 = g_nbr[p], j1 = g_nbr[p + 1], j2 = g_nbr[p + 2], j3 = g_nbr[p + 3];
        float4 v0 = up4(hp[(size_t)j0 * 32 + lane]);
        float4 v1 = up4(hp[(size_t)j1 * 32 + lane]);
        float4 v2 = up4(hp[(size_t)j2 * 32 + lane]);
        float4 v3 = up4(hp[(size_t)j3 * 32 + lane]);
        acc.x += v0.x + v1.x + v2.x + v3.x;
        acc.y += v0.y + v1.y + v2.y + v3.y;
        acc.z += v0.z + v1.z + v2.z + v3.z;
        acc.w += v0.w + v1.w + v2.w + v3.w;
    }
    for (; p < end; p++) {
        float4 v = up4(hp[(size_t)g_nbr[p] * 32 + lane]);
        acc.x += v.x; acc.y += v.y; acc.z += v.z; acc.w += v.w;
    }

    size_t o = (size_t)warp * 128 + lane * 4;
    *(uint2*)&z[o] = make_uint2(
        pack_h2(__float2half_rn(acc.x), __float2half_rn(acc.y)),
        pack_h2(__float2half_rn(acc.z), __float2half_rn(acc.w)));
}

// ---------------------------------------------------------------------------
// Weight prep (all 7): W[K][N] fp32 -> transposed fp16 [N][K]
// ---------------------------------------------------------------------------
struct WSeg { const float* src; int K, N, off; };
struct WAll { WSeg s[7]; };

__global__ void wprep_all(WAll wa, __half* __restrict__ hi) {
    int i = blockIdx.x * blockDim.x + threadIdx.x;
    #pragma unroll
    for (int j = 0; j < 7; j++) {
        WSeg sg = wa.s[j];
        int loc = i - sg.off;
        if (loc >= 0 && loc < sg.K * sg.N) {
            int k = loc / sg.N, n = loc % sg.N;
            hi[sg.off + n * sg.K + k] = __float2half_rn(sg.src[loc]);
        }
    }
}

// x [M,64] fp32 -> fp16
__global__ void xprep_kernel(const float* __restrict__ x,
                             __half* __restrict__ hi, int n) {
    int i = blockIdx.x * blockDim.x + threadIdx.x;
    if (i >= n) return;
    hi[i] = __float2half_rn(x[i]);
}

// ---------------------------------------------------------------------------
// MMA helpers (fp16)
// ---------------------------------------------------------------------------
__device__ __forceinline__ void mma_f16(float c[4], const uint32_t a[4],
                                        uint32_t b0, uint32_t b1) {
    asm volatile(
        "mma.sync.aligned.m16n8k16.row.col.f32.f16.f16.f32 "
        "{%0,%1,%2,%3}, {%4,%5,%6,%7}, {%8,%9}, {%0,%1,%2,%3};"
        : "+f"(c[0]), "+f"(c[1]), "+f"(c[2]), "+f"(c[3])
        : "r"(a[0]), "r"(a[1]), "r"(a[2]), "r"(a[3]), "r"(b0), "r"(b1));
}

__device__ __forceinline__ void ldsm_x4(uint32_t r[4], uint32_t saddr) {
    asm volatile("ldmatrix.sync.aligned.m8n8.x4.shared.b16 {%0,%1,%2,%3}, [%4];"
                 : "=r"(r[0]), "=r"(r[1]), "=r"(r[2]), "=r"(r[3])
                 : "r"(saddr));
}

__device__ __forceinline__ void cp16(uint32_t saddr, const void* gaddr) {
    asm volatile("cp.async.ca.shared.global [%0], [%1], 16;"
                 :: "r"(saddr), "l"(gaddr) : "memory");
}

// ---------------------------------------------------------------------------
// Pure-fp16 tensor-core GEMM: C = act(A @ Wh + bias)
// CTA tile 128x128, BK=32, 8 warps (4x2), warp 32x64.
// OUTM: 0 = fp32 C, 2 = fp16 (Chi).
// ---------------------------------------------------------------------------
#define STG_ELEM  5120                    // 128*40 halves per array
#define STG_BYTES (2 * STG_ELEM * 2)      // 20480 bytes per stage (A + B)

template <int K, int NTOT, bool RELU, int OUTM>
__global__ __launch_bounds__(256, 2) void mma_gemm(
    const __half* __restrict__ A_g,
    const __half* __restrict__ Wh,
    const float* __restrict__ bias,
    float* __restrict__ C,
    __half* __restrict__ Chi,
    int M) {

    extern __shared__ __half smem[];
    const uint32_t sbase = (uint32_t)__cvta_generic_to_shared(smem);

    const int tid  = threadIdx.x;
    const int lane = tid & 31;
    const int warp = tid >> 5;
    const int wm   = warp >> 1;
    const int wn   = warp & 1;
    const int m0   = blockIdx.x * 128;
    const int n0   = blockIdx.y * 128;
    const int g    = lane >> 2;
    const int q4   = lane & 3;

    const int arow = (lane & 7) + ((lane >> 3) & 1) * 8;
    const int akq  = (lane >> 4) * 8;
    const int bn   = (lane & 7) + ((lane >> 4) & 1) * 8;
    const int bkq  = ((lane >> 3) & 1) * 8;

    uint32_t aBase[2], bBase[4];
    #pragma unroll
    for (int mt = 0; mt < 2; mt++) {
        int r = wm * 32 + mt * 16 + arow;
        aBase[mt] = sbase + (uint32_t)(r * 40 + akq) * 2;
    }
    #pragma unroll
    for (int ntp = 0; ntp < 4; ntp++) {
        int n = wn * 64 + ntp * 16 + bn;
        bBase[ntp] = sbase + (uint32_t)(STG_ELEM + n * 40 + bkq) * 2;
    }

    auto issue_tile = [&](int s, int k0) {
        uint32_t b = sbase + (uint32_t)s * STG_BYTES;
        #pragma unroll
        for (int rep = 0; rep < 2; rep++) {
            int i = tid + rep * 256;
            int row = i >> 2, q = i & 3;
            uint32_t so = (uint32_t)(row * 40 + q * 8) * 2;
            size_t ga = (size_t)(m0 + row) * K + k0 + q * 8;
            size_t gb = (size_t)(n0 + row) * K + k0 + q * 8;
            cp16(b + so, A_g + ga);
            cp16(b + STG_ELEM * 2 + so, Wh + gb);
        }
        asm volatile("cp.async.commit_group;");
    };

    float acc[2][8][4];
    #pragma unroll
    for (int mt = 0; mt < 2; mt++)
        #pragma unroll
        for (int nt = 0; nt < 8; nt++)
            #pragma unroll
            for (int j = 0; j < 4; j++) acc[mt][nt][j] = 0.0f;

    constexpr int NIT = K / 32;
    issue_tile(0, 0);

    #pragma unroll
    for (int it = 0; it < NIT; it++) {
        if (it + 1 < NIT) {
            issue_tile((it + 1) & 1, (it + 1) * 32);
            asm volatile("cp.async.wait_group 1;");
        } else {
            asm volatile("cp.async.wait_group 0;");
        }
        __syncthreads();

        const uint32_t st = (uint32_t)(it & 1) * STG_BYTES;
        #pragma unroll
        for (int ks = 0; ks < 32; ks += 16) {
            const uint32_t kofs = st + (uint32_t)ks * 2;
            uint32_t a[2][4];
            #pragma unroll
            for (int mt = 0; mt < 2; mt++)
                ldsm_x4(a[mt], aBase[mt] + kofs);
            uint32_t bh[4][4];
            #pragma unroll
            for (int ntp = 0; ntp < 4; ntp++)
                ldsm_x4(bh[ntp], bBase[ntp] + kofs);
            #pragma unroll
            for (int nt = 0; nt < 8; nt++) {
                uint32_t b0 = bh[nt >> 1][(nt & 1) * 2];
                uint32_t b1 = bh[nt >> 1][(nt & 1) * 2 + 1];
                #pragma unroll
                for (int mt = 0; mt < 2; mt++)
                    mma_f16(acc[mt][nt], a[mt], b0, b1);
            }
        }
        __syncthreads();
    }

    // ---- epilogue ----
    #pragma unroll
    for (int mt = 0; mt < 2; mt++) {
        #pragma unroll
        for (int nt = 0; nt < 8; nt++) {
            int c = n0 + wn * 64 + nt * 8 + 2 * q4;
            float2 bv = make_float2(0.f, 0.f);
            if (bias) bv = *(const float2*)&bias[c];
            int r = m0 + wm * 32 + mt * 16 + g;
            float2 o0, o1;
            o0.x = acc[mt][nt][0] + bv.x;
            o0.y = acc[mt][nt][1] + bv.y;
            o1.x = acc[mt][nt][2] + bv.x;
            o1.y = acc[mt][nt][3] + bv.y;
            if (RELU) {
                o0.x = fmaxf(o0.x, 0.f); o0.y = fmaxf(o0.y, 0.f);
                o1.x = fmaxf(o1.x, 0.f); o1.y = fmaxf(o1.y, 0.f);
            }
            #pragma unroll
            for (int half = 0; half < 2; half++) {
                int rr = r + half * 8;
                float2 o = half ? o1 : o0;
                if (rr < M) {
                    if (OUTM == 2) {
                        *(uint32_t*)&Chi[(size_t)rr * NTOT + c] =
                            pack_h2(__float2half_rn(o.x), __float2half_rn(o.y));
                    } else {
                        *(float2*)&C[(size_t)rr * NTOT + c] = o;
                    }
                }
            }
        }
    }
}

// ---------------------------------------------------------------------------
// Host side
// ---------------------------------------------------------------------------
static __half* s_whi;

template <int K, int NTOT, bool RELU, int OUTM>
static void run_gemm(const __half* A, int woff, const float* bias,
                     float* C, __half* Chi, int M) {
    cudaFuncSetAttribute(mma_gemm<K, NTOT, RELU, OUTM>,
                         cudaFuncAttributeMaxDynamicSharedMemorySize,
                         2 * STG_BYTES);
    dim3 grid((M + 127) / 128, NTOT / 128);
    mma_gemm<K, NTOT, RELU, OUTM><<<grid, 256, 2 * STG_BYTES>>>(
        A, s_whi + woff, bias, C, Chi, M);
}

extern "C" void kernel_launch(void* const* d_in, const int* in_sizes, int n_in,
                              void* d_out, int out_size) {
    const float* x       = (const float*)d_in[0];
    const void*  eidx    = d_in[1];
    const float* W_embed = (const float*)d_in[2];
    const float* eps1    = (const float*)d_in[3];
    const float* w1a     = (const float*)d_in[4];
    const float* b1a     = (const float*)d_in[5];
    const float* w1b     = (const float*)d_in[6];
    const float* b1b     = (const float*)d_in[7];
    const float* eps2    = (const float*)d_in[8];
    const float* w2a     = (const float*)d_in[9];
    const float* b2a     = (const float*)d_in[10];
    const float* w2b     = (const float*)d_in[11];
    const float* b2b     = (const float*)d_in[12];
    const float* eps3    = (const float*)d_in[13];
    const float* w3a     = (const float*)d_in[14];
    const float* b3a     = (const float*)d_in[15];
    const float* w3b     = (const float*)d_in[16];
    const float* b3b     = (const float*)d_in[17];

    const int M = in_sizes[0] / 64;
    const int E = in_sizes[1] / 2;

    __half *ph16, *pz16, *pt16;
    int *pdeg, *palloc;
    cudaGetSymbolAddress((void**)&ph16, g_h16);
    cudaGetSymbolAddress((void**)&pz16, g_z16);
    cudaGetSymbolAddress((void**)&pt16, g_t16);
    cudaGetSymbolAddress((void**)&s_whi, g_whi);
    cudaGetSymbolAddress((void**)&pdeg, g_deg);
    cudaGetSymbolAddress((void**)&palloc, g_alloc);
    float* out = (float*)d_out;

    const int eBlks   = (E + 255) / 256;
    const int aggBlks = (M + 7) / 8;

    static cudaStream_t s1 = nullptr;
    static cudaEvent_t evFork = nullptr, evJoin = nullptr;
    if (!s1) {
        cudaStreamCreateWithFlags(&s1, cudaStreamNonBlocking);
        cudaEventCreateWithFlags(&evFork, cudaEventDisableTiming);
        cudaEventCreateWithFlags(&evJoin, cudaEventDisableTiming);
    }

    // ---- fork: CSR build on s1 ----
    cudaEventRecord(evFork, 0);
    cudaStreamWaitEvent(s1, evFork, 0);

    cudaMemsetAsync(pdeg, 0, (size_t)M * sizeof(int), s1);
    cudaMemsetAsync(palloc, 0, sizeof(int), s1);
    detect_kernel<<<1, 1, 0, s1>>>((const int*)eidx);
    hist_kernel<<<eBlks, 256, 0, s1>>>(eidx, E);
    offsets_kernel<<<(M + 255) / 256, 256, 0, s1>>>(M);
    fill_kernel<<<eBlks, 256, 0, s1>>>(eidx, E);
    cudaEventRecord(evJoin, s1);

    // ---- main stream: weights + x prep + embed ----
    WAll wa;
    wa.s[0] = {W_embed,  64, 128, 0};
    wa.s[1] = {w1a, 128, 128, 8192};
    wa.s[2] = {w1b, 128, 128, 24576};
    wa.s[3] = {w2a, 128, 256, 40960};
    wa.s[4] = {w2b, 256, 128, 73728};
    wa.s[5] = {w3a, 128, 256, 106496};
    wa.s[6] = {w3b, 256, 128, 139264};
    wprep_all<<<(WTOTAL + 255) / 256, 256>>>(wa, s_whi);

    xprep_kernel<<<(M * 64 + 255) / 256, 256>>>(x, pt16, M * 64);

    // embed: h = x @ W_embed  (fp16 h out)
    run_gemm<64, 128, false, 2>(pt16, 0, nullptr, nullptr, ph16, M);

    cudaStreamWaitEvent(0, evJoin, 0);

    // ---- conv1 ----
    agg_kernel<<<aggBlks, 256>>>(ph16, pz16, eps1, M);
    run_gemm<128, 128, true,  2>(pz16, 8192,  b1a, nullptr, pt16, M);
    run_gemm<128, 128, false, 2>(pt16, 24576, b1b, nullptr, ph16, M);

    // ---- conv2 ----
    agg_kernel<<<aggBlks, 256>>>(ph16, pz16, eps2, M);
    run_gemm<128, 256, true, 2>(pz16, 40960, b2a, nullptr, pt16, M);
    run_gemm<256, 128, true, 2>(pt16, 73728, b2b, nullptr, ph16, M);

    // ---- conv3 ----
    agg_kernel<<<aggBlks, 256>>>(ph16, pz16, eps3, M);
    run_gemm<128, 256, true, 2>(pz16, 106496, b3a, nullptr, pt16, M);
    run_gemm<256, 128, true, 0>(pt16, 139264, b3b, out, nullptr, M);
}